// round 14
// baseline (speedup 1.0000x reference)
#include <cuda_runtime.h>
#include <cuda_fp16.h>
#include <math.h>
#include <stdint.h>

#define N_WORD 50000
#define N_DOC  10000
#define E_WW   800000
#define E_WD   320000

// ---------------- device scratch (static allocation only) ----------------
__device__ __half g_twn[(size_t)N_WORD * 384];  // [t_ww | t_wwr | t_wd] per word
__device__ float  g_tws[(size_t)N_WORD * 128];  // combined self transform (word)
__device__ __half g_tdn[(size_t)N_DOC * 128];   // t_wdr per doc
__device__ float  g_tds[(size_t)N_DOC * 128];   // self transform (doc)
__device__ float  g_xw[(size_t)N_WORD * 128];   // layer-1 word output
__device__ float  g_xd[(size_t)N_DOC * 128];    // layer-1 doc output
// Transposed fp16 concat weights: Bt[n][k], row stride = K of current layer
__device__ __half g_Bw[512 * 256];              // word weights (max K=256)
__device__ __half g_Bd[256 * 256];              // doc weights  (max K=256)

// CSR per relation: 0=ww, 1=wwr, 2=wd(dst=doc), 3=wdr
__device__ int g_ptr_ww[N_WORD + 1], g_ptr_wwr[N_WORD + 1], g_ptr_wdr[N_WORD + 1];
__device__ int g_ptr_wd[N_DOC + 1];
__device__ int g_cur_ww[N_WORD + 1], g_cur_wwr[N_WORD + 1], g_cur_wdr[N_WORD + 1];
__device__ int g_cur_wd[N_DOC + 1];
__device__ int g_col_ww[E_WW], g_col_wwr[E_WW], g_col_wd[E_WD], g_col_wdr[E_WD];

__device__ __forceinline__ int* cur_of(int rel) {
    switch (rel) { case 0: return g_cur_ww; case 1: return g_cur_wwr;
                   case 2: return g_cur_wd; default: return g_cur_wdr; }
}
__device__ __forceinline__ int* ptr_of(int rel) {
    switch (rel) { case 0: return g_ptr_ww; case 1: return g_ptr_wwr;
                   case 2: return g_ptr_wd; default: return g_ptr_wdr; }
}

// ---------------- CSR build ----------------
__global__ void zero_cnt_kernel() {
    int i = blockIdx.x * blockDim.x + threadIdx.x;
    if (i < N_WORD + 1) { g_cur_ww[i] = 0; g_cur_wwr[i] = 0; g_cur_wdr[i] = 0; }
    if (i < N_DOC + 1)  { g_cur_wd[i] = 0; }
}

__global__ void hist_all_kernel(const int* __restrict__ ww_dst, const int* __restrict__ wwr_dst,
                                const int* __restrict__ wd_dst, const int* __restrict__ wdr_dst) {
    const int total = 2 * E_WW + 2 * E_WD;
    for (int i = blockIdx.x * blockDim.x + threadIdx.x; i < total; i += gridDim.x * blockDim.x) {
        if (i < E_WW)                  atomicAdd(&g_cur_ww[ww_dst[i]], 1);
        else if (i < 2 * E_WW)         atomicAdd(&g_cur_wwr[wwr_dst[i - E_WW]], 1);
        else if (i < 2 * E_WW + E_WD)  atomicAdd(&g_cur_wd[wd_dst[i - 2 * E_WW]], 1);
        else                           atomicAdd(&g_cur_wdr[wdr_dst[i - 2 * E_WW - E_WD]], 1);
    }
}

__global__ void scan_all_kernel() {
    int rel = blockIdx.x;
    int n = (rel == 2) ? N_DOC : N_WORD;
    int* cnt = cur_of(rel);
    int* ptr = ptr_of(rel);
    __shared__ int sh_warp[32];
    __shared__ int sh_carry;
    if (threadIdx.x == 0) sh_carry = 0;
    __syncthreads();
    for (int base = 0; base < n; base += 1024) {
        int i = base + (int)threadIdx.x;
        int v = (i < n) ? cnt[i] : 0;
        int lane = threadIdx.x & 31, wid = threadIdx.x >> 5;
        int x = v;
        #pragma unroll
        for (int o = 1; o < 32; o <<= 1) { int y = __shfl_up_sync(0xffffffffu, x, o); if (lane >= o) x += y; }
        if (lane == 31) sh_warp[wid] = x;
        __syncthreads();
        if (wid == 0) {
            int s = sh_warp[lane];
            #pragma unroll
            for (int o = 1; o < 32; o <<= 1) { int y = __shfl_up_sync(0xffffffffu, s, o); if (lane >= o) s += y; }
            sh_warp[lane] = s;
        }
        __syncthreads();
        int pre = (wid > 0) ? sh_warp[wid - 1] : 0;
        int incl = x + pre + sh_carry;
        if (i < n) { int excl = incl - v; ptr[i] = excl; cnt[i] = excl; }
        __syncthreads();
        if (threadIdx.x == 1023) sh_carry = incl;
        __syncthreads();
    }
    if (threadIdx.x == 0) { ptr[n] = sh_carry; cnt[n] = sh_carry; }
}

__global__ void scatter_all_kernel(const int* __restrict__ ww_src, const int* __restrict__ ww_dst,
                                   const int* __restrict__ wwr_src, const int* __restrict__ wwr_dst,
                                   const int* __restrict__ wd_src, const int* __restrict__ wd_dst,
                                   const int* __restrict__ wdr_src, const int* __restrict__ wdr_dst) {
    const int total = 2 * E_WW + 2 * E_WD;
    for (int i = blockIdx.x * blockDim.x + threadIdx.x; i < total; i += gridDim.x * blockDim.x) {
        if (i < E_WW) {
            int p = atomicAdd(&g_cur_ww[ww_dst[i]], 1);  g_col_ww[p] = ww_src[i];
        } else if (i < 2 * E_WW) {
            int j = i - E_WW;
            int p = atomicAdd(&g_cur_wwr[wwr_dst[j]], 1); g_col_wwr[p] = wwr_src[j];
        } else if (i < 2 * E_WW + E_WD) {
            int j = i - 2 * E_WW;
            int p = atomicAdd(&g_cur_wd[wd_dst[j]], 1);   g_col_wd[p] = wd_src[j];
        } else {
            int j = i - 2 * E_WW - E_WD;
            int p = atomicAdd(&g_cur_wdr[wdr_dst[j]], 1); g_col_wdr[p] = wdr_src[j];
        }
    }
}

// ---------------- weight concat prep: transpose to Bt[n][k], convert fp16 ----------------
__global__ void prep_w_kernel(const float* __restrict__ Ws, const float* __restrict__ Wn, int K) {
    int i = blockIdx.x * blockDim.x + threadIdx.x;
    if (i >= K * 128) return;
    int n = i / K, k = i % K;
    int KN = K * 128;
    g_Bw[(size_t)(0   + n) * K + k] = __float2half(Wn[0 * KN + k * 128 + n]);
    g_Bw[(size_t)(128 + n) * K + k] = __float2half(Wn[1 * KN + k * 128 + n]);
    g_Bw[(size_t)(256 + n) * K + k] = __float2half(Wn[2 * KN + k * 128 + n]);
    g_Bw[(size_t)(384 + n) * K + k] = __float2half(Ws[0 * KN + k * 128 + n]
                                                 + Ws[1 * KN + k * 128 + n]
                                                 + Ws[3 * KN + k * 128 + n]);
}
__global__ void prep_d_kernel(const float* __restrict__ Ws, const float* __restrict__ Wn, int K) {
    int i = blockIdx.x * blockDim.x + threadIdx.x;
    if (i >= K * 128) return;
    int n = i / K, k = i % K;
    int KN = K * 128;
    g_Bd[(size_t)(0   + n) * K + k] = __float2half(Wn[3 * KN + k * 128 + n]);
    g_Bd[(size_t)(128 + n) * K + k] = __float2half(Ws[2 * KN + k * 128 + n]);
}

// ---------------- fp16 tensor-core GEMM: C[M,N] = A[M,K] @ Bt[N,K]^T ----------------
#define GBK 32
#define AST 40

// a_sel: 0 ext, 1 g_xw, 2 g_xd ; b_sel: 0 g_Bw, 1 g_Bd ; c_sel: 0 word, 1 doc
__global__ __launch_bounds__(256) void gemm_fp16_kernel(const float* __restrict__ a_ext,
                                                        int a_sel, int b_sel, int c_sel,
                                                        int M, int K, int N) {
    const float* A = (a_sel == 0) ? a_ext : (a_sel == 1 ? (const float*)g_xw : (const float*)g_xd);
    const __half* Bt = (b_sel == 0) ? (const __half*)g_Bw : (const __half*)g_Bd;

    __shared__ __half As[128][AST];
    __shared__ __half Bs[128][AST];

    const int tid = threadIdx.x;
    const int warp = tid >> 5, lane = tid & 31;
    const int g = lane >> 2, t = lane & 3;
    const int wm0 = (warp & 1) * 64;
    const int wn0 = (warp >> 1) * 32;
    const int row0 = blockIdx.y * 128, col0 = blockIdx.x * 128;

    float c[4][4][4];
    #pragma unroll
    for (int i = 0; i < 4; ++i)
        #pragma unroll
        for (int j = 0; j < 4; ++j)
            #pragma unroll
            for (int r = 0; r < 4; ++r) c[i][j][r] = 0.0f;

    const int srow = tid >> 1;
    const int scol = (tid & 1) * 16;

    for (int k0 = 0; k0 < K; k0 += GBK) {
        {
            int gr = row0 + srow;
            if (gr < M) {
                const float* ap = A + (size_t)gr * K + k0 + scol;
                #pragma unroll
                for (int q = 0; q < 4; ++q) {
                    float4 v = *reinterpret_cast<const float4*>(ap + 4 * q);
                    __half2 p0 = __float22half2_rn(make_float2(v.x, v.y));
                    __half2 p1 = __float22half2_rn(make_float2(v.z, v.w));
                    uint2 u;
                    u.x = *reinterpret_cast<uint32_t*>(&p0);
                    u.y = *reinterpret_cast<uint32_t*>(&p1);
                    *reinterpret_cast<uint2*>(&As[srow][scol + 4 * q]) = u;
                }
            } else {
                #pragma unroll
                for (int q = 0; q < 4; ++q)
                    *reinterpret_cast<uint2*>(&As[srow][scol + 4 * q]) = make_uint2(0u, 0u);
            }
        }
        {
            const __half* bp = Bt + (size_t)(col0 + srow) * K + k0 + scol;
            uint4 u0 = *reinterpret_cast<const uint4*>(bp);
            uint4 u1 = *reinterpret_cast<const uint4*>(bp + 8);
            *reinterpret_cast<uint4*>(&Bs[srow][scol])     = u0;
            *reinterpret_cast<uint4*>(&Bs[srow][scol + 8]) = u1;
        }
        __syncthreads();

        #pragma unroll
        for (int kk = 0; kk < GBK; kk += 16) {
            uint32_t af[4][4], bf[4][2];
            #pragma unroll
            for (int i = 0; i < 4; ++i) {
                int r = wm0 + i * 16 + g;
                af[i][0] = *reinterpret_cast<const uint32_t*>(&As[r][kk + 2 * t]);
                af[i][1] = *reinterpret_cast<const uint32_t*>(&As[r + 8][kk + 2 * t]);
                af[i][2] = *reinterpret_cast<const uint32_t*>(&As[r][kk + 8 + 2 * t]);
                af[i][3] = *reinterpret_cast<const uint32_t*>(&As[r + 8][kk + 8 + 2 * t]);
            }
            #pragma unroll
            for (int j = 0; j < 4; ++j) {
                int nn = wn0 + j * 8 + g;
                bf[j][0] = *reinterpret_cast<const uint32_t*>(&Bs[nn][kk + 2 * t]);
                bf[j][1] = *reinterpret_cast<const uint32_t*>(&Bs[nn][kk + 8 + 2 * t]);
            }
            #pragma unroll
            for (int i = 0; i < 4; ++i)
                #pragma unroll
                for (int j = 0; j < 4; ++j) {
                    asm volatile(
                        "mma.sync.aligned.m16n8k16.row.col.f32.f16.f16.f32 "
                        "{%0,%1,%2,%3}, {%4,%5,%6,%7}, {%8,%9}, {%0,%1,%2,%3};"
                        : "+f"(c[i][j][0]), "+f"(c[i][j][1]), "+f"(c[i][j][2]), "+f"(c[i][j][3])
                        : "r"(af[i][0]), "r"(af[i][1]), "r"(af[i][2]), "r"(af[i][3]),
                          "r"(bf[j][0]), "r"(bf[j][1]));
                }
        }
        __syncthreads();
    }

    const int self0 = (c_sel == 0) ? 384 : 128;
    __half* HN = (c_sel == 0) ? g_twn : g_tdn;
    float*  FS = (c_sel == 0) ? g_tws : g_tds;
    const int hn_stride = self0;

    #pragma unroll
    for (int i = 0; i < 4; ++i) {
        #pragma unroll
        for (int hrow = 0; hrow < 2; ++hrow) {
            int r = row0 + wm0 + i * 16 + g + hrow * 8;
            if (r >= M) continue;
            #pragma unroll
            for (int j = 0; j < 4; ++j) {
                int cc = col0 + wn0 + j * 8 + 2 * t;
                float v0 = c[i][j][hrow * 2 + 0], v1 = c[i][j][hrow * 2 + 1];
                if (cc < self0) {
                    *reinterpret_cast<__half2*>(HN + (size_t)r * hn_stride + cc) =
                        __float22half2_rn(make_float2(v0, v1));
                } else {
                    *reinterpret_cast<float2*>(FS + (size_t)r * 128 + (cc - self0)) =
                        make_float2(v0, v1);
                }
            }
        }
    }
}

// ---------------- aggregation + combine (R6-proven ILP4 gather) ----------------
__device__ __forceinline__ void acc_h4(float4& acc, const __half* __restrict__ p) {
    uint2 u = *reinterpret_cast<const uint2*>(p);
    __half2 h0 = *reinterpret_cast<const __half2*>(&u.x);
    __half2 h1 = *reinterpret_cast<const __half2*>(&u.y);
    float2 a = __half22float2(h0);
    float2 b = __half22float2(h1);
    acc.x += a.x; acc.y += a.y; acc.z += b.x; acc.w += b.y;
}

__device__ __forceinline__ float4 gather_mean_h(const __half* __restrict__ t, int stride, int base,
                                                const int* __restrict__ ptr,
                                                const int* __restrict__ col, int v, int c4) {
    int beg = ptr[v], end = ptr[v + 1];
    float4 a0 = make_float4(0.f, 0.f, 0.f, 0.f);
    float4 a1 = make_float4(0.f, 0.f, 0.f, 0.f);
    float4 a2 = make_float4(0.f, 0.f, 0.f, 0.f);
    float4 a3 = make_float4(0.f, 0.f, 0.f, 0.f);
    int e = beg;
    for (; e + 4 <= end; e += 4) {
        int s0 = col[e], s1 = col[e + 1], s2 = col[e + 2], s3 = col[e + 3];
        acc_h4(a0, t + (size_t)s0 * stride + base + c4);
        acc_h4(a1, t + (size_t)s1 * stride + base + c4);
        acc_h4(a2, t + (size_t)s2 * stride + base + c4);
        acc_h4(a3, t + (size_t)s3 * stride + base + c4);
    }
    for (; e < end; ++e) {
        int s = col[e];
        acc_h4(a0, t + (size_t)s * stride + base + c4);
    }
    a0.x += a1.x + a2.x + a3.x;
    a0.y += a1.y + a2.y + a3.y;
    a0.z += a1.z + a2.z + a3.z;
    a0.w += a1.w + a2.w + a3.w;
    int d = end - beg;
    float inv = 1.0f / (float)(d > 0 ? d : 1);
    a0.x *= inv; a0.y *= inv; a0.z *= inv; a0.w *= inv;
    return a0;
}

template <bool FINAL>
__global__ void combine_word_kernel(const float* __restrict__ b,
                                    const float* __restrict__ lin_w,
                                    const float* __restrict__ lin_b,
                                    float* __restrict__ out) {
    int warp = (blockIdx.x * blockDim.x + threadIdx.x) >> 5;
    if (warp >= N_WORD) return;
    int lane = threadIdx.x & 31;
    int c4 = lane * 4;
    int v = warp;

    float4 h = *reinterpret_cast<const float4*>(g_tws + (size_t)v * 128 + c4);
    float4 m0 = gather_mean_h(g_twn, 384, 0,   g_ptr_ww,  g_col_ww,  v, c4);
    float4 m1 = gather_mean_h(g_twn, 384, 128, g_ptr_wwr, g_col_wwr, v, c4);
    float4 m3 = gather_mean_h(g_tdn, 128, 0,   g_ptr_wdr, g_col_wdr, v, c4);

    h.x = fmaxf(h.x + m0.x + m1.x + m3.x + b[c4 + 0] + b[128 + c4 + 0] + b[384 + c4 + 0], 0.f);
    h.y = fmaxf(h.y + m0.y + m1.y + m3.y + b[c4 + 1] + b[128 + c4 + 1] + b[384 + c4 + 1], 0.f);
    h.z = fmaxf(h.z + m0.z + m1.z + m3.z + b[c4 + 2] + b[128 + c4 + 2] + b[384 + c4 + 2], 0.f);
    h.w = fmaxf(h.w + m0.w + m1.w + m3.w + b[c4 + 3] + b[128 + c4 + 3] + b[384 + c4 + 3], 0.f);

    if (!FINAL) {
        *reinterpret_cast<float4*>(g_xw + (size_t)v * 128 + c4) = h;
    } else {
        float4 lw = *reinterpret_cast<const float4*>(lin_w + c4);
        float p = h.x * lw.x + h.y * lw.y + h.z * lw.z + h.w * lw.w;
        #pragma unroll
        for (int o = 16; o > 0; o >>= 1) p += __shfl_down_sync(0xffffffffu, p, o);
        if (lane == 0) out[v] = 1.0f / (1.0f + expf(-(p + lin_b[0])));
    }
}

template <bool FINAL>
__global__ void combine_doc_kernel(const float* __restrict__ b,
                                   const float* __restrict__ lin_w,
                                   const float* __restrict__ lin_b,
                                   float* __restrict__ out) {
    int warp = (blockIdx.x * blockDim.x + threadIdx.x) >> 5;
    if (warp >= N_DOC) return;
    int lane = threadIdx.x & 31;
    int c4 = lane * 4;
    int v = warp;

    float4 h = *reinterpret_cast<const float4*>(g_tds + (size_t)v * 128 + c4);
    float4 m2 = gather_mean_h(g_twn, 384, 256, g_ptr_wd, g_col_wd, v, c4);

    h.x = fmaxf(h.x + m2.x + b[256 + c4 + 0], 0.f);
    h.y = fmaxf(h.y + m2.y + b[256 + c4 + 1], 0.f);
    h.z = fmaxf(h.z + m2.z + b[256 + c4 + 2], 0.f);
    h.w = fmaxf(h.w + m2.w + b[256 + c4 + 3], 0.f);

    if (!FINAL) {
        *reinterpret_cast<float4*>(g_xd + (size_t)v * 128 + c4) = h;
    } else {
        float4 lw = *reinterpret_cast<const float4*>(lin_w + c4);
        float p = h.x * lw.x + h.y * lw.y + h.z * lw.z + h.w * lw.w;
        #pragma unroll
        for (int o = 16; o > 0; o >>= 1) p += __shfl_down_sync(0xffffffffu, p, o);
        if (lane == 0) out[N_WORD + v] = 1.0f / (1.0f + expf(-(p + lin_b[0])));
    }
}

// ---------------- host launch ----------------
extern "C" void kernel_launch(void* const* d_in, const int* in_sizes, int n_in,
                              void* d_out, int out_size) {
    const float* x_word  = (const float*)d_in[0];
    const float* x_doc   = (const float*)d_in[1];
    const int*   ww_src  = (const int*)d_in[2];
    const int*   ww_dst  = (const int*)d_in[3];
    const int*   wwr_src = (const int*)d_in[4];
    const int*   wwr_dst = (const int*)d_in[5];
    const int*   wd_src  = (const int*)d_in[6];
    const int*   wd_dst  = (const int*)d_in[7];
    const int*   wdr_src = (const int*)d_in[8];
    const int*   wdr_dst = (const int*)d_in[9];
    const float* Wself1  = (const float*)d_in[10];
    const float* Wneigh1 = (const float*)d_in[11];
    const float* b1      = (const float*)d_in[12];
    const float* Wself2  = (const float*)d_in[13];
    const float* Wneigh2 = (const float*)d_in[14];
    const float* b2      = (const float*)d_in[15];
    const float* lin_w   = (const float*)d_in[16];
    const float* lin_b   = (const float*)d_in[17];
    float* out = (float*)d_out;

    static cudaStream_t s_csr = nullptr, s_doc = nullptr;
    static cudaEvent_t ev_fork, ev_csr, ev_w1, ev_d1, ev_wc1, ev_dc1, ev_w2, ev_d2, ev_ddone;
    if (s_csr == nullptr) {
        cudaStreamCreateWithFlags(&s_csr, cudaStreamNonBlocking);
        cudaStreamCreateWithFlags(&s_doc, cudaStreamNonBlocking);
        cudaEventCreateWithFlags(&ev_fork, cudaEventDisableTiming);
        cudaEventCreateWithFlags(&ev_csr, cudaEventDisableTiming);
        cudaEventCreateWithFlags(&ev_w1, cudaEventDisableTiming);
        cudaEventCreateWithFlags(&ev_d1, cudaEventDisableTiming);
        cudaEventCreateWithFlags(&ev_wc1, cudaEventDisableTiming);
        cudaEventCreateWithFlags(&ev_dc1, cudaEventDisableTiming);
        cudaEventCreateWithFlags(&ev_w2, cudaEventDisableTiming);
        cudaEventCreateWithFlags(&ev_d2, cudaEventDisableTiming);
        cudaEventCreateWithFlags(&ev_ddone, cudaEventDisableTiming);
    }

    // fork
    cudaEventRecord(ev_fork, 0);
    cudaStreamWaitEvent(s_csr, ev_fork, 0);
    cudaStreamWaitEvent(s_doc, ev_fork, 0);

    // CSR stream
    zero_cnt_kernel<<<(N_WORD + 256) / 256, 256, 0, s_csr>>>();
    hist_all_kernel<<<1184, 256, 0, s_csr>>>(ww_dst, wwr_dst, wd_dst, wdr_dst);
    scan_all_kernel<<<4, 1024, 0, s_csr>>>();
    scatter_all_kernel<<<1184, 256, 0, s_csr>>>(ww_src, ww_dst, wwr_src, wwr_dst,
                                                wd_src, wd_dst, wdr_src, wdr_dst);
    cudaEventRecord(ev_csr, s_csr);

    // doc chain on s_doc
    prep_d_kernel<<<(256 * 128 + 255) / 256, 256, 0, s_doc>>>(Wself1, Wneigh1, 256);
    gemm_fp16_kernel<<<dim3(2, (N_DOC + 127) / 128), 256, 0, s_doc>>>(x_doc, 0, 1, 1, N_DOC, 256, 256);
    cudaEventRecord(ev_d1, s_doc);
    // prep_d2 overwrites g_Bd after gemm_d1 (same-stream ordered)
    prep_d_kernel<<<(128 * 128 + 255) / 256, 256, 0, s_doc>>>(Wself2, Wneigh2, 128);

    // word chain on main (0)
    prep_w_kernel<<<(256 * 128 + 255) / 256, 256>>>(Wself1, Wneigh1, 256);
    gemm_fp16_kernel<<<dim3(4, (N_WORD + 127) / 128), 256>>>(x_word, 0, 0, 0, N_WORD, 256, 512);
    cudaEventRecord(ev_w1, 0);

    // combine word L1: needs w1 (stream-ordered), d1 (g_tdn), csr
    cudaStreamWaitEvent(0, ev_d1, 0);
    cudaStreamWaitEvent(0, ev_csr, 0);
    combine_word_kernel<false><<<(N_WORD + 7) / 8, 256>>>(b1, lin_w, lin_b, out);
    cudaEventRecord(ev_wc1, 0);

    // combine doc L1 on s_doc: needs d1 (ordered), w1 (g_twn[256:384]), csr
    cudaStreamWaitEvent(s_doc, ev_w1, 0);
    cudaStreamWaitEvent(s_doc, ev_csr, 0);
    combine_doc_kernel<false><<<(N_DOC + 7) / 8, 256, 0, s_doc>>>(b1, lin_w, lin_b, out);
    cudaEventRecord(ev_dc1, s_doc);

    // word L2: prep_w2 after gemm_w1 (ordered); gemm_w2 overwrites g_twn -> wait combine_doc L1
    prep_w_kernel<<<(128 * 128 + 255) / 256, 256>>>(Wself2, Wneigh2, 128);
    cudaStreamWaitEvent(0, ev_dc1, 0);
    gemm_fp16_kernel<<<dim3(4, (N_WORD + 127) / 128), 256>>>(nullptr, 1, 0, 0, N_WORD, 128, 512);
    cudaEventRecord(ev_w2, 0);

    // doc L2 on s_doc: gemm_d2 overwrites g_tdn -> wait combine_word L1
    cudaStreamWaitEvent(s_doc, ev_wc1, 0);
    gemm_fp16_kernel<<<dim3(2, (N_DOC + 127) / 128), 256, 0, s_doc>>>(nullptr, 2, 1, 1, N_DOC, 128, 256);
    cudaEventRecord(ev_d2, s_doc);

    // finals: word needs d2 (g_tdn), doc needs w2 (g_twn[256:384])
    cudaStreamWaitEvent(0, ev_d2, 0);
    combine_word_kernel<true><<<(N_WORD + 7) / 8, 256>>>(b2, lin_w, lin_b, out);

    cudaStreamWaitEvent(s_doc, ev_w2, 0);
    combine_doc_kernel<true><<<(N_DOC + 7) / 8, 256, 0, s_doc>>>(b2, lin_w, lin_b, out);
    cudaEventRecord(ev_ddone, s_doc);

    // join
    cudaStreamWaitEvent(0, ev_ddone, 0);
}

// round 16
// speedup vs baseline: 1.0493x; 1.0493x over previous
#include <cuda_runtime.h>
#include <cuda_fp16.h>
#include <math.h>
#include <stdint.h>

#define N_WORD 50000
#define N_DOC  10000
#define E_WW   800000
#define E_WD   320000

// ---------------- device scratch (static allocation only) ----------------
__device__ __half g_twn[(size_t)N_WORD * 384];  // [t_ww | t_wwr | t_wd] per word
__device__ float  g_tws[(size_t)N_WORD * 128];  // combined self transform (word)
__device__ __half g_tdn[(size_t)N_DOC * 128];   // t_wdr per doc
__device__ float  g_tds[(size_t)N_DOC * 128];   // self transform (doc)
__device__ float  g_xw[(size_t)N_WORD * 128];   // layer-1 word output
__device__ float  g_xd[(size_t)N_DOC * 128];    // layer-1 doc output
// Transposed fp16 concat weights: Bt[n][k], row stride = K of current layer
__device__ __half g_Bw[512 * 256];              // word weights (max K=256)
__device__ __half g_Bd[256 * 256];              // doc weights  (max K=256)

// CSR per relation: 0=ww, 1=wwr, 2=wd(dst=doc), 3=wdr
__device__ int g_ptr_ww[N_WORD + 1], g_ptr_wwr[N_WORD + 1], g_ptr_wdr[N_WORD + 1];
__device__ int g_ptr_wd[N_DOC + 1];
__device__ int g_cur_ww[N_WORD + 1], g_cur_wwr[N_WORD + 1], g_cur_wdr[N_WORD + 1];
__device__ int g_cur_wd[N_DOC + 1];
__device__ int g_col_ww[E_WW], g_col_wwr[E_WW], g_col_wd[E_WD], g_col_wdr[E_WD];

__device__ __forceinline__ int* cur_of(int rel) {
    switch (rel) { case 0: return g_cur_ww; case 1: return g_cur_wwr;
                   case 2: return g_cur_wd; default: return g_cur_wdr; }
}
__device__ __forceinline__ int* ptr_of(int rel) {
    switch (rel) { case 0: return g_ptr_ww; case 1: return g_ptr_wwr;
                   case 2: return g_ptr_wd; default: return g_ptr_wdr; }
}

// ---------------- CSR build ----------------
__global__ void zero_cnt_kernel() {
    int i = blockIdx.x * blockDim.x + threadIdx.x;
    if (i < N_WORD + 1) { g_cur_ww[i] = 0; g_cur_wwr[i] = 0; g_cur_wdr[i] = 0; }
    if (i < N_DOC + 1)  { g_cur_wd[i] = 0; }
}

__global__ void hist_all_kernel(const int* __restrict__ ww_dst, const int* __restrict__ wwr_dst,
                                const int* __restrict__ wd_dst, const int* __restrict__ wdr_dst) {
    const int total = 2 * E_WW + 2 * E_WD;
    for (int i = blockIdx.x * blockDim.x + threadIdx.x; i < total; i += gridDim.x * blockDim.x) {
        if (i < E_WW)                  atomicAdd(&g_cur_ww[ww_dst[i]], 1);
        else if (i < 2 * E_WW)         atomicAdd(&g_cur_wwr[wwr_dst[i - E_WW]], 1);
        else if (i < 2 * E_WW + E_WD)  atomicAdd(&g_cur_wd[wd_dst[i - 2 * E_WW]], 1);
        else                           atomicAdd(&g_cur_wdr[wdr_dst[i - 2 * E_WW - E_WD]], 1);
    }
}

__global__ void scan_all_kernel() {
    int rel = blockIdx.x;
    int n = (rel == 2) ? N_DOC : N_WORD;
    int* cnt = cur_of(rel);
    int* ptr = ptr_of(rel);
    __shared__ int sh_warp[32];
    __shared__ int sh_carry;
    if (threadIdx.x == 0) sh_carry = 0;
    __syncthreads();
    for (int base = 0; base < n; base += 1024) {
        int i = base + (int)threadIdx.x;
        int v = (i < n) ? cnt[i] : 0;
        int lane = threadIdx.x & 31, wid = threadIdx.x >> 5;
        int x = v;
        #pragma unroll
        for (int o = 1; o < 32; o <<= 1) { int y = __shfl_up_sync(0xffffffffu, x, o); if (lane >= o) x += y; }
        if (lane == 31) sh_warp[wid] = x;
        __syncthreads();
        if (wid == 0) {
            int s = sh_warp[lane];
            #pragma unroll
            for (int o = 1; o < 32; o <<= 1) { int y = __shfl_up_sync(0xffffffffu, s, o); if (lane >= o) s += y; }
            sh_warp[lane] = s;
        }
        __syncthreads();
        int pre = (wid > 0) ? sh_warp[wid - 1] : 0;
        int incl = x + pre + sh_carry;
        if (i < n) { int excl = incl - v; ptr[i] = excl; cnt[i] = excl; }
        __syncthreads();
        if (threadIdx.x == 1023) sh_carry = incl;
        __syncthreads();
    }
    if (threadIdx.x == 0) { ptr[n] = sh_carry; cnt[n] = sh_carry; }
}

__global__ void scatter_all_kernel(const int* __restrict__ ww_src, const int* __restrict__ ww_dst,
                                   const int* __restrict__ wwr_src, const int* __restrict__ wwr_dst,
                                   const int* __restrict__ wd_src, const int* __restrict__ wd_dst,
                                   const int* __restrict__ wdr_src, const int* __restrict__ wdr_dst) {
    const int total = 2 * E_WW + 2 * E_WD;
    for (int i = blockIdx.x * blockDim.x + threadIdx.x; i < total; i += gridDim.x * blockDim.x) {
        if (i < E_WW) {
            int p = atomicAdd(&g_cur_ww[ww_dst[i]], 1);  g_col_ww[p] = ww_src[i];
        } else if (i < 2 * E_WW) {
            int j = i - E_WW;
            int p = atomicAdd(&g_cur_wwr[wwr_dst[j]], 1); g_col_wwr[p] = wwr_src[j];
        } else if (i < 2 * E_WW + E_WD) {
            int j = i - 2 * E_WW;
            int p = atomicAdd(&g_cur_wd[wd_dst[j]], 1);   g_col_wd[p] = wd_src[j];
        } else {
            int j = i - 2 * E_WW - E_WD;
            int p = atomicAdd(&g_cur_wdr[wdr_dst[j]], 1); g_col_wdr[p] = wdr_src[j];
        }
    }
}

// ---------------- weight concat prep: transpose to Bt[n][k], convert fp16 ----------------
__global__ void prep_w_kernel(const float* __restrict__ Ws, const float* __restrict__ Wn, int K) {
    int i = blockIdx.x * blockDim.x + threadIdx.x;
    if (i >= K * 128) return;
    int n = i / K, k = i % K;
    int KN = K * 128;
    g_Bw[(size_t)(0   + n) * K + k] = __float2half(Wn[0 * KN + k * 128 + n]);
    g_Bw[(size_t)(128 + n) * K + k] = __float2half(Wn[1 * KN + k * 128 + n]);
    g_Bw[(size_t)(256 + n) * K + k] = __float2half(Wn[2 * KN + k * 128 + n]);
    g_Bw[(size_t)(384 + n) * K + k] = __float2half(Ws[0 * KN + k * 128 + n]
                                                 + Ws[1 * KN + k * 128 + n]
                                                 + Ws[3 * KN + k * 128 + n]);
}
__global__ void prep_d_kernel(const float* __restrict__ Ws, const float* __restrict__ Wn, int K) {
    int i = blockIdx.x * blockDim.x + threadIdx.x;
    if (i >= K * 128) return;
    int n = i / K, k = i % K;
    int KN = K * 128;
    g_Bd[(size_t)(0   + n) * K + k] = __float2half(Wn[3 * KN + k * 128 + n]);
    g_Bd[(size_t)(128 + n) * K + k] = __float2half(Ws[2 * KN + k * 128 + n]);
}

// ---------------- fp16 tensor-core GEMM, double-buffered + register prefetch ----------------
#define GBK 32
#define AST 40

// a_sel: 0 ext, 1 g_xw, 2 g_xd ; b_sel: 0 g_Bw, 1 g_Bd ; c_sel: 0 word, 1 doc
__global__ __launch_bounds__(256) void gemm_fp16_kernel(const float* __restrict__ a_ext,
                                                        int a_sel, int b_sel, int c_sel,
                                                        int M, int K, int N) {
    const float* A = (a_sel == 0) ? a_ext : (a_sel == 1 ? (const float*)g_xw : (const float*)g_xd);
    const __half* Bt = (b_sel == 0) ? (const __half*)g_Bw : (const __half*)g_Bd;

    __shared__ __half As[2][128][AST];
    __shared__ __half Bs[2][128][AST];

    const int tid = threadIdx.x;
    const int warp = tid >> 5, lane = tid & 31;
    const int g = lane >> 2, t = lane & 3;
    const int wm0 = (warp & 1) * 64;
    const int wn0 = (warp >> 1) * 32;
    const int row0 = blockIdx.y * 128, col0 = blockIdx.x * 128;

    float c[4][4][4];
    #pragma unroll
    for (int i = 0; i < 4; ++i)
        #pragma unroll
        for (int j = 0; j < 4; ++j)
            #pragma unroll
            for (int r = 0; r < 4; ++r) c[i][j][r] = 0.0f;

    const int srow = tid >> 1;         // 0..127
    const int scol = (tid & 1) * 16;   // 0 or 16
    const int gr = row0 + srow;
    const bool arow_ok = (gr < M);
    const float* aptr = A + (size_t)gr * K + scol;
    const __half* bptr = Bt + (size_t)(col0 + srow) * K + scol;

    float4 av[4];
    uint4 bv[2];

    // ---- prefetch chunk 0 into registers ----
    if (arow_ok) {
        #pragma unroll
        for (int q = 0; q < 4; ++q) av[q] = *reinterpret_cast<const float4*>(aptr + 4 * q);
    } else {
        #pragma unroll
        for (int q = 0; q < 4; ++q) av[q] = make_float4(0.f, 0.f, 0.f, 0.f);
    }
    bv[0] = *reinterpret_cast<const uint4*>(bptr);
    bv[1] = *reinterpret_cast<const uint4*>(bptr + 8);

    // ---- store chunk 0 into buffer 0 ----
    #pragma unroll
    for (int q = 0; q < 4; ++q) {
        __half2 p0 = __float22half2_rn(make_float2(av[q].x, av[q].y));
        __half2 p1 = __float22half2_rn(make_float2(av[q].z, av[q].w));
        uint2 u;
        u.x = *reinterpret_cast<uint32_t*>(&p0);
        u.y = *reinterpret_cast<uint32_t*>(&p1);
        *reinterpret_cast<uint2*>(&As[0][srow][scol + 4 * q]) = u;
    }
    *reinterpret_cast<uint4*>(&Bs[0][srow][scol])     = bv[0];
    *reinterpret_cast<uint4*>(&Bs[0][srow][scol + 8]) = bv[1];
    __syncthreads();

    const int nk = K / GBK;
    for (int kt = 0; kt < nk; ++kt) {
        const int cur = kt & 1;
        const bool more = (kt + 1 < nk);

        // prefetch chunk kt+1 (LDGs in flight during MMA below)
        if (more) {
            int k0 = (kt + 1) * GBK;
            if (arow_ok) {
                #pragma unroll
                for (int q = 0; q < 4; ++q)
                    av[q] = *reinterpret_cast<const float4*>(aptr + k0 + 4 * q);
            }
            bv[0] = *reinterpret_cast<const uint4*>(bptr + k0);
            bv[1] = *reinterpret_cast<const uint4*>(bptr + k0 + 8);
        }

        // MMA over buffer cur
        #pragma unroll
        for (int kk = 0; kk < GBK; kk += 16) {
            uint32_t af[4][4], bf[4][2];
            #pragma unroll
            for (int i = 0; i < 4; ++i) {
                int r = wm0 + i * 16 + g;
                af[i][0] = *reinterpret_cast<const uint32_t*>(&As[cur][r][kk + 2 * t]);
                af[i][1] = *reinterpret_cast<const uint32_t*>(&As[cur][r + 8][kk + 2 * t]);
                af[i][2] = *reinterpret_cast<const uint32_t*>(&As[cur][r][kk + 8 + 2 * t]);
                af[i][3] = *reinterpret_cast<const uint32_t*>(&As[cur][r + 8][kk + 8 + 2 * t]);
            }
            #pragma unroll
            for (int j = 0; j < 4; ++j) {
                int nn = wn0 + j * 8 + g;
                bf[j][0] = *reinterpret_cast<const uint32_t*>(&Bs[cur][nn][kk + 2 * t]);
                bf[j][1] = *reinterpret_cast<const uint32_t*>(&Bs[cur][nn][kk + 8 + 2 * t]);
            }
            #pragma unroll
            for (int i = 0; i < 4; ++i)
                #pragma unroll
                for (int j = 0; j < 4; ++j) {
                    asm volatile(
                        "mma.sync.aligned.m16n8k16.row.col.f32.f16.f16.f32 "
                        "{%0,%1,%2,%3}, {%4,%5,%6,%7}, {%8,%9}, {%0,%1,%2,%3};"
                        : "+f"(c[i][j][0]), "+f"(c[i][j][1]), "+f"(c[i][j][2]), "+f"(c[i][j][3])
                        : "r"(af[i][0]), "r"(af[i][1]), "r"(af[i][2]), "r"(af[i][3]),
                          "r"(bf[j][0]), "r"(bf[j][1]));
                }
        }

        // store chunk kt+1 into the other buffer, then barrier
        if (more) {
            const int nxt = (kt + 1) & 1;
            #pragma unroll
            for (int q = 0; q < 4; ++q) {
                float4 v = arow_ok ? av[q] : make_float4(0.f, 0.f, 0.f, 0.f);
                __half2 p0 = __float22half2_rn(make_float2(v.x, v.y));
                __half2 p1 = __float22half2_rn(make_float2(v.z, v.w));
                uint2 u;
                u.x = *reinterpret_cast<uint32_t*>(&p0);
                u.y = *reinterpret_cast<uint32_t*>(&p1);
                *reinterpret_cast<uint2*>(&As[nxt][srow][scol + 4 * q]) = u;
            }
            *reinterpret_cast<uint4*>(&Bs[nxt][srow][scol])     = bv[0];
            *reinterpret_cast<uint4*>(&Bs[nxt][srow][scol + 8]) = bv[1];
            __syncthreads();
        }
    }

    // epilogue: split fp16 neighbor / fp32 self
    const int self0 = (c_sel == 0) ? 384 : 128;
    __half* HN = (c_sel == 0) ? g_twn : g_tdn;
    float*  FS = (c_sel == 0) ? g_tws : g_tds;
    const int hn_stride = self0;

    #pragma unroll
    for (int i = 0; i < 4; ++i) {
        #pragma unroll
        for (int hrow = 0; hrow < 2; ++hrow) {
            int r = row0 + wm0 + i * 16 + g + hrow * 8;
            if (r >= M) continue;
            #pragma unroll
            for (int j = 0; j < 4; ++j) {
                int cc = col0 + wn0 + j * 8 + 2 * t;
                float v0 = c[i][j][hrow * 2 + 0], v1 = c[i][j][hrow * 2 + 1];
                if (cc < self0) {
                    *reinterpret_cast<__half2*>(HN + (size_t)r * hn_stride + cc) =
                        __float22half2_rn(make_float2(v0, v1));
                } else {
                    *reinterpret_cast<float2*>(FS + (size_t)r * 128 + (cc - self0)) =
                        make_float2(v0, v1);
                }
            }
        }
    }
}

// ---------------- aggregation + combine (R6-proven ILP4 gather) ----------------
__device__ __forceinline__ void acc_h4(float4& acc, const __half* __restrict__ p) {
    uint2 u = *reinterpret_cast<const uint2*>(p);
    __half2 h0 = *reinterpret_cast<const __half2*>(&u.x);
    __half2 h1 = *reinterpret_cast<const __half2*>(&u.y);
    float2 a = __half22float2(h0);
    float2 b = __half22float2(h1);
    acc.x += a.x; acc.y += a.y; acc.z += b.x; acc.w += b.y;
}

__device__ __forceinline__ float4 gather_mean_h(const __half* __restrict__ t, int stride, int base,
                                                const int* __restrict__ ptr,
                                                const int* __restrict__ col, int v, int c4) {
    int beg = ptr[v], end = ptr[v + 1];
    float4 a0 = make_float4(0.f, 0.f, 0.f, 0.f);
    float4 a1 = make_float4(0.f, 0.f, 0.f, 0.f);
    float4 a2 = make_float4(0.f, 0.f, 0.f, 0.f);
    float4 a3 = make_float4(0.f, 0.f, 0.f, 0.f);
    int e = beg;
    for (; e + 4 <= end; e += 4) {
        int s0 = col[e], s1 = col[e + 1], s2 = col[e + 2], s3 = col[e + 3];
        acc_h4(a0, t + (size_t)s0 * stride + base + c4);
        acc_h4(a1, t + (size_t)s1 * stride + base + c4);
        acc_h4(a2, t + (size_t)s2 * stride + base + c4);
        acc_h4(a3, t + (size_t)s3 * stride + base + c4);
    }
    for (; e < end; ++e) {
        int s = col[e];
        acc_h4(a0, t + (size_t)s * stride + base + c4);
    }
    a0.x += a1.x + a2.x + a3.x;
    a0.y += a1.y + a2.y + a3.y;
    a0.z += a1.z + a2.z + a3.z;
    a0.w += a1.w + a2.w + a3.w;
    int d = end - beg;
    float inv = 1.0f / (float)(d > 0 ? d : 1);
    a0.x *= inv; a0.y *= inv; a0.z *= inv; a0.w *= inv;
    return a0;
}

template <bool FINAL>
__global__ void combine_word_kernel(const float* __restrict__ b,
                                    const float* __restrict__ lin_w,
                                    const float* __restrict__ lin_b,
                                    float* __restrict__ out) {
    int warp = (blockIdx.x * blockDim.x + threadIdx.x) >> 5;
    if (warp >= N_WORD) return;
    int lane = threadIdx.x & 31;
    int c4 = lane * 4;
    int v = warp;

    float4 h = *reinterpret_cast<const float4*>(g_tws + (size_t)v * 128 + c4);
    float4 m0 = gather_mean_h(g_twn, 384, 0,   g_ptr_ww,  g_col_ww,  v, c4);
    float4 m1 = gather_mean_h(g_twn, 384, 128, g_ptr_wwr, g_col_wwr, v, c4);
    float4 m3 = gather_mean_h(g_tdn, 128, 0,   g_ptr_wdr, g_col_wdr, v, c4);

    h.x = fmaxf(h.x + m0.x + m1.x + m3.x + b[c4 + 0] + b[128 + c4 + 0] + b[384 + c4 + 0], 0.f);
    h.y = fmaxf(h.y + m0.y + m1.y + m3.y + b[c4 + 1] + b[128 + c4 + 1] + b[384 + c4 + 1], 0.f);
    h.z = fmaxf(h.z + m0.z + m1.z + m3.z + b[c4 + 2] + b[128 + c4 + 2] + b[384 + c4 + 2], 0.f);
    h.w = fmaxf(h.w + m0.w + m1.w + m3.w + b[c4 + 3] + b[128 + c4 + 3] + b[384 + c4 + 3], 0.f);

    if (!FINAL) {
        *reinterpret_cast<float4*>(g_xw + (size_t)v * 128 + c4) = h;
    } else {
        float4 lw = *reinterpret_cast<const float4*>(lin_w + c4);
        float p = h.x * lw.x + h.y * lw.y + h.z * lw.z + h.w * lw.w;
        #pragma unroll
        for (int o = 16; o > 0; o >>= 1) p += __shfl_down_sync(0xffffffffu, p, o);
        if (lane == 0) out[v] = 1.0f / (1.0f + expf(-(p + lin_b[0])));
    }
}

template <bool FINAL>
__global__ void combine_doc_kernel(const float* __restrict__ b,
                                   const float* __restrict__ lin_w,
                                   const float* __restrict__ lin_b,
                                   float* __restrict__ out) {
    int warp = (blockIdx.x * blockDim.x + threadIdx.x) >> 5;
    if (warp >= N_DOC) return;
    int lane = threadIdx.x & 31;
    int c4 = lane * 4;
    int v = warp;

    float4 h = *reinterpret_cast<const float4*>(g_tds + (size_t)v * 128 + c4);
    float4 m2 = gather_mean_h(g_twn, 384, 256, g_ptr_wd, g_col_wd, v, c4);

    h.x = fmaxf(h.x + m2.x + b[256 + c4 + 0], 0.f);
    h.y = fmaxf(h.y + m2.y + b[256 + c4 + 1], 0.f);
    h.z = fmaxf(h.z + m2.z + b[256 + c4 + 2], 0.f);
    h.w = fmaxf(h.w + m2.w + b[256 + c4 + 3], 0.f);

    if (!FINAL) {
        *reinterpret_cast<float4*>(g_xd + (size_t)v * 128 + c4) = h;
    } else {
        float4 lw = *reinterpret_cast<const float4*>(lin_w + c4);
        float p = h.x * lw.x + h.y * lw.y + h.z * lw.z + h.w * lw.w;
        #pragma unroll
        for (int o = 16; o > 0; o >>= 1) p += __shfl_down_sync(0xffffffffu, p, o);
        if (lane == 0) out[N_WORD + v] = 1.0f / (1.0f + expf(-(p + lin_b[0])));
    }
}

// ---------------- host launch (R13 schedule) ----------------
extern "C" void kernel_launch(void* const* d_in, const int* in_sizes, int n_in,
                              void* d_out, int out_size) {
    const float* x_word  = (const float*)d_in[0];
    const float* x_doc   = (const float*)d_in[1];
    const int*   ww_src  = (const int*)d_in[2];
    const int*   ww_dst  = (const int*)d_in[3];
    const int*   wwr_src = (const int*)d_in[4];
    const int*   wwr_dst = (const int*)d_in[5];
    const int*   wd_src  = (const int*)d_in[6];
    const int*   wd_dst  = (const int*)d_in[7];
    const int*   wdr_src = (const int*)d_in[8];
    const int*   wdr_dst = (const int*)d_in[9];
    const float* Wself1  = (const float*)d_in[10];
    const float* Wneigh1 = (const float*)d_in[11];
    const float* b1      = (const float*)d_in[12];
    const float* Wself2  = (const float*)d_in[13];
    const float* Wneigh2 = (const float*)d_in[14];
    const float* b2      = (const float*)d_in[15];
    const float* lin_w   = (const float*)d_in[16];
    const float* lin_b   = (const float*)d_in[17];
    float* out = (float*)d_out;

    static cudaStream_t s_csr = nullptr;
    static cudaEvent_t ev_fork = nullptr, ev_csr = nullptr;
    if (s_csr == nullptr) {
        cudaStreamCreateWithFlags(&s_csr, cudaStreamNonBlocking);
        cudaEventCreateWithFlags(&ev_fork, cudaEventDisableTiming);
        cudaEventCreateWithFlags(&ev_csr, cudaEventDisableTiming);
    }

    // fork: CSR build runs on s_csr concurrently with layer-1 GEMMs on stream 0
    cudaEventRecord(ev_fork, 0);
    cudaStreamWaitEvent(s_csr, ev_fork, 0);

    zero_cnt_kernel<<<(N_WORD + 256) / 256, 256, 0, s_csr>>>();
    hist_all_kernel<<<1184, 256, 0, s_csr>>>(ww_dst, wwr_dst, wd_dst, wdr_dst);
    scan_all_kernel<<<4, 1024, 0, s_csr>>>();
    scatter_all_kernel<<<1184, 256, 0, s_csr>>>(ww_src, ww_dst, wwr_src, wwr_dst,
                                                wd_src, wd_dst, wdr_src, wdr_dst);
    cudaEventRecord(ev_csr, s_csr);

    // --- layer 1 (K = 256) ---
    prep_w_kernel<<<(256 * 128 + 255) / 256, 256>>>(Wself1, Wneigh1, 256);
    prep_d_kernel<<<(256 * 128 + 255) / 256, 256>>>(Wself1, Wneigh1, 256);
    gemm_fp16_kernel<<<dim3(4, (N_WORD + 127) / 128), 256>>>(x_word, 0, 0, 0, N_WORD, 256, 512);
    gemm_fp16_kernel<<<dim3(2, (N_DOC + 127) / 128), 256>>>(x_doc, 0, 1, 1, N_DOC, 256, 256);

    cudaStreamWaitEvent(0, ev_csr, 0);
    combine_word_kernel<false><<<(N_WORD + 7) / 8, 256>>>(b1, lin_w, lin_b, out);
    combine_doc_kernel<false><<<(N_DOC + 7) / 8, 256>>>(b1, lin_w, lin_b, out);

    // --- layer 2 (K = 128) + fused final linear/sigmoid ---
    prep_w_kernel<<<(128 * 128 + 255) / 256, 256>>>(Wself2, Wneigh2, 128);
    prep_d_kernel<<<(128 * 128 + 255) / 256, 256>>>(Wself2, Wneigh2, 128);
    gemm_fp16_kernel<<<dim3(4, (N_WORD + 127) / 128), 256>>>(nullptr, 1, 0, 0, N_WORD, 128, 512);
    gemm_fp16_kernel<<<dim3(2, (N_DOC + 127) / 128), 256>>>(nullptr, 2, 1, 1, N_DOC, 128, 256);
    combine_word_kernel<true><<<(N_WORD + 7) / 8, 256>>>(b2, lin_w, lin_b, out);
    combine_doc_kernel<true><<<(N_DOC + 7) / 8, 256>>>(b2, lin_w, lin_b, out);
}